// round 5
// baseline (speedup 1.0000x reference)
#include <cuda_runtime.h>
#include <math.h>

static constexpr int Bc  = 2;
static constexpr int Sc  = 2048;
static constexpr int Dc  = 1024;
static constexpr int Hc  = 16;
static constexpr int HDc = 64;
static constexpr int Mtot = Bc * Sc;   // 4096

// Scratch (device globals: allocation-free rule). ~67MB total.
__device__ float g_q[(size_t)Bc * Hc * Sc * HDc];      // [B,H,S,HD]
__device__ float g_k[(size_t)Bc * Hc * Sc * HDc];
__device__ float g_v[(size_t)Bc * Hc * Sc * HDc];
__device__ float g_ctx[(size_t)Bc * Sc * Dc];          // [B,S,D]

// ---------------------------------------------------------------------------
// tf32 helpers
// ---------------------------------------------------------------------------
__device__ __forceinline__ unsigned f2tf(float x) {
    unsigned r;
    asm("cvt.rna.tf32.f32 %0, %1;" : "=r"(r) : "f"(x));
    return r;
}

__device__ __forceinline__ void mma8(float c[4], const unsigned a[4], const unsigned b[2]) {
    asm volatile(
        "mma.sync.aligned.m16n8k8.row.col.f32.tf32.tf32.f32 "
        "{%0,%1,%2,%3}, {%4,%5,%6,%7}, {%8,%9}, {%0,%1,%2,%3};"
        : "+f"(c[0]), "+f"(c[1]), "+f"(c[2]), "+f"(c[3])
        : "r"(a[0]), "r"(a[1]), "r"(a[2]), "r"(a[3]), "r"(b[0]), "r"(b[1]));
}

// ---------------------------------------------------------------------------
// tf32 MMA GEMM: C = A[M,K] @ B[K,N] + bias  (projections)
// Pair-interleaved smem: element k of an 8-wide k-group lives at
//   slab (kg*4 + (k&3)), half (k>>2)&1  ->  fragment loads are LDS.64.
// Slab stride 264 words (== 8 banks mod 32) -> conflict-free frag loads.
// EPI 0: row-major C = acc + bias.  EPI 1: permuted [B,H,S,HD], *scale.
// 128x128x32 block tile, warps 2x4 (64x32), 256 threads.
// ---------------------------------------------------------------------------
template <int EPI>
__global__ __launch_bounds__(256)
void mma_gemm(const float* __restrict__ A, const float* __restrict__ B,
              const float* __restrict__ bias, float* __restrict__ C,
              float scale)
{
    constexpr int MI = 4, NI = 4;       // WM=64, WN=32
    constexpr int Kd = 1024;
    constexpr int SLAB = 264;           // 128*2 + 8 pad words

    __shared__ __align__(16) unsigned As2[16 * SLAB];   // [kg*4+slot][m][2]
    __shared__ __align__(16) unsigned Bs2[16 * SLAB];   // [kg*4+slot][n][2]

    const int tid = threadIdx.x;
    const int m0 = blockIdx.y * 128;
    const int n0 = blockIdx.x * 128;

    const int w    = tid >> 5;
    const int lane = tid & 31;
    const int wr   = w & 1;
    const int wc   = w >> 1;
    const int lg   = lane >> 2;
    const int lt   = lane & 3;

    float acc[MI][NI][4];
#pragma unroll
    for (int mi = 0; mi < MI; mi++)
#pragma unroll
        for (int ni = 0; ni < NI; ni++)
#pragma unroll
            for (int r = 0; r < 4; r++) acc[mi][ni][r] = 0.f;

    for (int k0 = 0; k0 < Kd; k0 += 32) {
        // ---- stage A tile ----
#pragma unroll
        for (int i = 0; i < 4; i++) {
            const int id = tid + i * 256;
            const int r  = id >> 3;         // m, 0..127
            const int c4 = id & 7;          // k-quad
            float4 v = *(const float4*)(A + (size_t)(m0 + r) * Kd + k0 + c4 * 4);
            const int kg   = c4 >> 1;
            const int half = c4 & 1;
            const int base = r * 2 + half;
            As2[(kg * 4 + 0) * SLAB + base] = f2tf(v.x);
            As2[(kg * 4 + 1) * SLAB + base] = f2tf(v.y);
            As2[(kg * 4 + 2) * SLAB + base] = f2tf(v.z);
            As2[(kg * 4 + 3) * SLAB + base] = f2tf(v.w);
        }
        // ---- stage B tile ----
#pragma unroll
        for (int i = 0; i < 4; i++) {
            const int id = tid + i * 256;
            const int r  = id >> 5;         // k, 0..31
            const int c4 = id & 31;         // n-quad
            float4 v = *(const float4*)(B + (size_t)(k0 + r) * Dc + n0 + c4 * 4);
            const int kg   = r >> 3;
            const int kw   = r & 7;
            const unsigned base = (kg * 4 + (kw & 3)) * SLAB + (kw >> 2);
            Bs2[base + (c4 * 4 + 0) * 2] = f2tf(v.x);
            Bs2[base + (c4 * 4 + 1) * 2] = f2tf(v.y);
            Bs2[base + (c4 * 4 + 2) * 2] = f2tf(v.z);
            Bs2[base + (c4 * 4 + 3) * 2] = f2tf(v.w);
        }
        __syncthreads();

#pragma unroll
        for (int kg = 0; kg < 4; kg++) {
            const unsigned soff = (kg * 4 + lt) * SLAB;
            unsigned af[MI][4], bf[NI][2];
#pragma unroll
            for (int mi = 0; mi < MI; mi++) {
                const int rb = wr * 64 + mi * 16;
                uint2 pa = *(const uint2*)&As2[soff + (rb + lg) * 2];
                uint2 pb = *(const uint2*)&As2[soff + (rb + lg + 8) * 2];
                af[mi][0] = pa.x; af[mi][1] = pb.x;
                af[mi][2] = pa.y; af[mi][3] = pb.y;
            }
#pragma unroll
            for (int ni = 0; ni < NI; ni++) {
                const int nb = wc * 32 + ni * 8;
                uint2 pq = *(const uint2*)&Bs2[soff + (nb + lg) * 2];
                bf[ni][0] = pq.x; bf[ni][1] = pq.y;
            }
#pragma unroll
            for (int mi = 0; mi < MI; mi++)
#pragma unroll
                for (int ni = 0; ni < NI; ni++)
                    mma8(acc[mi][ni], af[mi], bf[ni]);
        }
        __syncthreads();
    }

#pragma unroll
    for (int mi = 0; mi < MI; mi++) {
#pragma unroll
        for (int ni = 0; ni < NI; ni++) {
            const int gmb = m0 + wr * 64 + mi * 16 + lg;
            const int gn  = n0 + wc * 32 + ni * 8 + lt * 2;
#pragma unroll
            for (int hh = 0; hh < 2; hh++) {
                const int gm = gmb + hh * 8;
                const float v0 = acc[mi][ni][hh * 2 + 0];
                const float v1 = acc[mi][ni][hh * 2 + 1];
                if (EPI == 0) {
                    *(float2*)&C[(size_t)gm * Dc + gn] =
                        make_float2(v0 + bias[gn], v1 + bias[gn + 1]);
                } else {
                    float2 r = make_float2((v0 + bias[gn]) * scale,
                                           (v1 + bias[gn + 1]) * scale);
                    const int b = gm >> 11, s = gm & 2047;
                    const int hd = gn & 63, hq = gn >> 6;
                    *(float2*)&C[(((size_t)(b * Hc + hq) * Sc) + s) * HDc + hd] = r;
                }
            }
        }
    }
}

// ---------------------------------------------------------------------------
// Fused tensor-core flash attention (tf32 MMA, fp32 accum).
// Block: one (b,h), 128 queries; 8 warps x 16 rows. Key tiles of 64.
// Pair-interleaved K/V smem (same scheme as GEMM): B-frag loads are LDS.64,
// slab stride 136 words (== 8 banks mod 32) -> conflict-free.
// Q pre-scaled by 1/sqrt(HD). Softmax fully warp-local (quad shuffles).
// P C-frag -> A-frag conversion via register shuffles.
// ---------------------------------------------------------------------------
__global__ __launch_bounds__(256)
void fattn(const float* __restrict__ Q, const float* __restrict__ K,
           const float* __restrict__ V, const float* __restrict__ mask,
           float* __restrict__ Octx)
{
    constexpr int SLAB = 136;   // 64*2 + 8 pad words

    __shared__ __align__(16) unsigned Ks2[32 * SLAB];  // [kf*4+slot][key][2]
    __shared__ __align__(16) unsigned Vs2[32 * SLAB];  // [kf*4+slot][hd][2]
    __shared__ float Msk[64];

    const int tid  = threadIdx.x;
    const int w    = tid >> 5;
    const int lane = tid & 31;
    const int lg   = lane >> 2;
    const int lt   = lane & 3;

    const int bh = blockIdx.y;
    const int b  = bh >> 4;
    const int h  = bh & 15;
    const int q0 = blockIdx.x * 128 + w * 16;

    // Q fragments (one-time gmem gather, rows q0+lg / q0+lg+8)
    const float* Qb = Q + ((size_t)bh * Sc + q0) * HDc;
    unsigned qf[8][4];
#pragma unroll
    for (int kf = 0; kf < 8; kf++) {
        qf[kf][0] = f2tf(__ldg(Qb + (size_t)(lg    ) * HDc + kf * 8 + lt    ));
        qf[kf][1] = f2tf(__ldg(Qb + (size_t)(lg + 8) * HDc + kf * 8 + lt    ));
        qf[kf][2] = f2tf(__ldg(Qb + (size_t)(lg    ) * HDc + kf * 8 + lt + 4));
        qf[kf][3] = f2tf(__ldg(Qb + (size_t)(lg + 8) * HDc + kf * 8 + lt + 4));
    }

    float acc_o[8][4];
#pragma unroll
    for (int no = 0; no < 8; no++)
#pragma unroll
        for (int r = 0; r < 4; r++) acc_o[no][r] = 0.f;
    float m_lo = -1e30f, m_hi = -1e30f, l_lo = 0.f, l_hi = 0.f;

    const float* Kb = K + (size_t)bh * Sc * HDc;
    const float* Vb = V + (size_t)bh * Sc * HDc;
    const float* Mb = mask + (size_t)b * Sc;

    for (int kt = 0; kt < Sc; kt += 64) {
        // ---- stage mask + K + V tiles (pair-interleaved tf32) ----
        if (tid < 64) Msk[tid] = Mb[kt + tid];
#pragma unroll
        for (int i = 0; i < 4; i++) {
            const int idx = tid + i * 256;          // 0..1023
            {
                // K: element (key, hd): slab = (hd>>3)*4 + (hd&3), half=(hd>>2)&1
                const int key = idx & 63;
                const int h4  = idx >> 6;           // 0..15
                float4 kv = *(const float4*)(Kb + (size_t)(kt + key) * HDc + h4 * 4);
                const int kf   = h4 >> 1;
                const int half = h4 & 1;
                const int base = key * 2 + half;
                Ks2[(kf * 4 + 0) * SLAB + base] = f2tf(kv.x);
                Ks2[(kf * 4 + 1) * SLAB + base] = f2tf(kv.y);
                Ks2[(kf * 4 + 2) * SLAB + base] = f2tf(kv.z);
                Ks2[(kf * 4 + 3) * SLAB + base] = f2tf(kv.w);
            }
            {
                // V: element (key, hd): slab = (key>>3)*4 + (key&3), half=(key>>2)&1
                const int key = idx >> 4;           // 0..63
                const int h4  = idx & 15;
                float4 vv = *(const float4*)(Vb + (size_t)(kt + key) * HDc + h4 * 4);
                const int kg = key >> 3;
                const int kw = key & 7;
                const unsigned base = (kg * 4 + (kw & 3)) * SLAB + (kw >> 2);
                Vs2[base + (h4 * 4 + 0) * 2] = f2tf(vv.x);
                Vs2[base + (h4 * 4 + 1) * 2] = f2tf(vv.y);
                Vs2[base + (h4 * 4 + 2) * 2] = f2tf(vv.z);
                Vs2[base + (h4 * 4 + 3) * 2] = f2tf(vv.w);
            }
        }
        __syncthreads();

        // ---- S = Q K^T (16 rows x 64 keys per warp) ----
        float sc[8][4];
#pragma unroll
        for (int ni = 0; ni < 8; ni++)
#pragma unroll
            for (int r = 0; r < 4; r++) sc[ni][r] = 0.f;
#pragma unroll
        for (int kf = 0; kf < 8; kf++) {
            const unsigned soff = (kf * 4 + lt) * SLAB;
#pragma unroll
            for (int ni = 0; ni < 8; ni++) {
                uint2 p = *(const uint2*)&Ks2[soff + (ni * 8 + lg) * 2];
                unsigned bf[2] = { p.x, p.y };
                mma8(sc[ni], qf[kf], bf);
            }
        }

        // ---- mask + online softmax (quad-local) ----
        float rmax_lo = -1e30f, rmax_hi = -1e30f;
#pragma unroll
        for (int ni = 0; ni < 8; ni++) {
            const float mk0 = Msk[ni * 8 + 2 * lt];
            const float mk1 = Msk[ni * 8 + 2 * lt + 1];
            sc[ni][0] += mk0; sc[ni][1] += mk1;
            sc[ni][2] += mk0; sc[ni][3] += mk1;
            rmax_lo = fmaxf(rmax_lo, fmaxf(sc[ni][0], sc[ni][1]));
            rmax_hi = fmaxf(rmax_hi, fmaxf(sc[ni][2], sc[ni][3]));
        }
        rmax_lo = fmaxf(rmax_lo, __shfl_xor_sync(0xffffffffu, rmax_lo, 1));
        rmax_lo = fmaxf(rmax_lo, __shfl_xor_sync(0xffffffffu, rmax_lo, 2));
        rmax_hi = fmaxf(rmax_hi, __shfl_xor_sync(0xffffffffu, rmax_hi, 1));
        rmax_hi = fmaxf(rmax_hi, __shfl_xor_sync(0xffffffffu, rmax_hi, 2));

        const float mn_lo = fmaxf(m_lo, rmax_lo);
        const float mn_hi = fmaxf(m_hi, rmax_hi);
        const float al_lo = __expf(m_lo - mn_lo);
        const float al_hi = __expf(m_hi - mn_hi);
        m_lo = mn_lo; m_hi = mn_hi;

        float ps_lo = 0.f, ps_hi = 0.f;
#pragma unroll
        for (int ni = 0; ni < 8; ni++) {
            sc[ni][0] = __expf(sc[ni][0] - m_lo);
            sc[ni][1] = __expf(sc[ni][1] - m_lo);
            sc[ni][2] = __expf(sc[ni][2] - m_hi);
            sc[ni][3] = __expf(sc[ni][3] - m_hi);
            ps_lo += sc[ni][0] + sc[ni][1];
            ps_hi += sc[ni][2] + sc[ni][3];
        }
        l_lo = l_lo * al_lo + ps_lo;
        l_hi = l_hi * al_hi + ps_hi;
#pragma unroll
        for (int no = 0; no < 8; no++) {
            acc_o[no][0] *= al_lo; acc_o[no][1] *= al_lo;
            acc_o[no][2] *= al_hi; acc_o[no][3] *= al_hi;
        }

        // ---- PV: convert P C-frag -> A-frag via shuffles, then MMA ----
        const int src_lo = (lane & 28) | (lt >> 1);
        const int src_hi = src_lo + 2;
#pragma unroll
        for (int kf = 0; kf < 8; kf++) {
            unsigned a[4];
            {
                float v0 = __shfl_sync(0xffffffffu, sc[kf][0], src_lo);
                float v1 = __shfl_sync(0xffffffffu, sc[kf][1], src_lo);
                a[0] = f2tf((lt & 1) ? v1 : v0);
                float v2 = __shfl_sync(0xffffffffu, sc[kf][2], src_lo);
                float v3 = __shfl_sync(0xffffffffu, sc[kf][3], src_lo);
                a[1] = f2tf((lt & 1) ? v3 : v2);
                float u0 = __shfl_sync(0xffffffffu, sc[kf][0], src_hi);
                float u1 = __shfl_sync(0xffffffffu, sc[kf][1], src_hi);
                a[2] = f2tf((lt & 1) ? u1 : u0);
                float u2 = __shfl_sync(0xffffffffu, sc[kf][2], src_hi);
                float u3 = __shfl_sync(0xffffffffu, sc[kf][3], src_hi);
                a[3] = f2tf((lt & 1) ? u3 : u2);
            }
            const unsigned soff = (kf * 4 + lt) * SLAB;
#pragma unroll
            for (int no = 0; no < 8; no++) {
                uint2 p = *(const uint2*)&Vs2[soff + (no * 8 + lg) * 2];
                unsigned bf[2] = { p.x, p.y };
                mma8(acc_o[no], a, bf);
            }
        }
        __syncthreads();
    }

    // ---- finalize: normalize and write ctx [B,S,D] ----
    l_lo += __shfl_xor_sync(0xffffffffu, l_lo, 1);
    l_lo += __shfl_xor_sync(0xffffffffu, l_lo, 2);
    l_hi += __shfl_xor_sync(0xffffffffu, l_hi, 1);
    l_hi += __shfl_xor_sync(0xffffffffu, l_hi, 2);
    const float inv_lo = 1.f / l_lo;
    const float inv_hi = 1.f / l_hi;

    float* Ob = Octx + ((size_t)b * Sc + q0) * Dc + h * HDc;
#pragma unroll
    for (int no = 0; no < 8; no++) {
        const int col = no * 8 + 2 * lt;
        *(float2*)(Ob + (size_t)(lg    ) * Dc + col) =
            make_float2(acc_o[no][0] * inv_lo, acc_o[no][1] * inv_lo);
        *(float2*)(Ob + (size_t)(lg + 8) * Dc + col) =
            make_float2(acc_o[no][2] * inv_hi, acc_o[no][3] * inv_hi);
    }
}

// ---------------------------------------------------------------------------
extern "C" void kernel_launch(void* const* d_in, const int* in_sizes, int n_in,
                              void* d_out, int out_size)
{
    const float* x    = (const float*)d_in[0];
    const float* mask = (const float*)d_in[1];
    const float* Wq   = (const float*)d_in[2];
    const float* bq   = (const float*)d_in[3];
    const float* Wk   = (const float*)d_in[4];
    const float* bk   = (const float*)d_in[5];
    const float* Wv   = (const float*)d_in[6];
    const float* bv   = (const float*)d_in[7];
    const float* Wo   = (const float*)d_in[8];
    const float* bo   = (const float*)d_in[9];
    float* out = (float*)d_out;

    void *qv, *kv, *vv, *cv;
    cudaGetSymbolAddress(&qv, g_q);
    cudaGetSymbolAddress(&kv, g_k);
    cudaGetSymbolAddress(&vv, g_v);
    cudaGetSymbolAddress(&cv, g_ctx);
    float* q   = (float*)qv;
    float* k   = (float*)kv;
    float* v   = (float*)vv;
    float* ctx = (float*)cv;

    dim3 g1(Dc / 128, Mtot / 128);   // (8, 32)
    mma_gemm<1><<<g1, 256>>>(x, Wq, bq, q, 0.125f);   // 1/sqrt(64)
    mma_gemm<1><<<g1, 256>>>(x, Wk, bk, k, 1.0f);
    mma_gemm<1><<<g1, 256>>>(x, Wv, bv, v, 1.0f);

    fattn<<<dim3(Sc / 128, Bc * Hc), 256>>>(q, k, v, mask, ctx);

    mma_gemm<0><<<g1, 256>>>(ctx, Wo, bo, out, 1.0f);
}

// round 6
// speedup vs baseline: 1.2495x; 1.2495x over previous
#include <cuda_runtime.h>
#include <math.h>

static constexpr int Bc  = 2;
static constexpr int Sc  = 2048;
static constexpr int Dc  = 1024;
static constexpr int Hc  = 16;
static constexpr int HDc = 64;
static constexpr int Mtot = Bc * Sc;   // 4096

// Scratch (device globals: allocation-free rule). ~67MB total.
__device__ float g_q[(size_t)Bc * Hc * Sc * HDc];      // [B,H,S,HD]
__device__ float g_k[(size_t)Bc * Hc * Sc * HDc];
__device__ float g_v[(size_t)Bc * Hc * Sc * HDc];
__device__ float g_ctx[(size_t)Bc * Sc * Dc];          // [B,S,D]

// ---------------------------------------------------------------------------
// tf32 helpers
// ---------------------------------------------------------------------------
__device__ __forceinline__ unsigned f2tf(float x) {
    unsigned r;
    asm("cvt.rna.tf32.f32 %0, %1;" : "=r"(r) : "f"(x));
    return r;
}

__device__ __forceinline__ void mma8(float c[4], const unsigned a[4], const unsigned b[2]) {
    asm volatile(
        "mma.sync.aligned.m16n8k8.row.col.f32.tf32.tf32.f32 "
        "{%0,%1,%2,%3}, {%4,%5,%6,%7}, {%8,%9}, {%0,%1,%2,%3};"
        : "+f"(c[0]), "+f"(c[1]), "+f"(c[2]), "+f"(c[3])
        : "r"(a[0]), "r"(a[1]), "r"(a[2]), "r"(a[3]), "r"(b[0]), "r"(b[1]));
}

// ---------------------------------------------------------------------------
// tf32 MMA GEMM: C = A[M,K] @ B[K,N] + bias  (projections)
// Register-prefetch pipeline: LDG tile k+1 into regs BEFORE computing tile k
// from smem, STS after the read-release sync. Hides global-load latency.
// EPI 0: row-major C = acc + bias.  EPI 1: permuted [B,H,S,HD], *scale.
// 128x128x32 block tile, warps 2x4 (64x32), 256 threads.
// ---------------------------------------------------------------------------
template <int EPI>
__global__ __launch_bounds__(256)
void mma_gemm(const float* __restrict__ A, const float* __restrict__ B,
              const float* __restrict__ bias, float* __restrict__ C,
              float scale)
{
    constexpr int BK = 32;
    constexpr int MI = 4, NI = 4;   // WM=64, WN=32
    constexpr int Kd = 1024;

    __shared__ unsigned As[BK][128 + 8];
    __shared__ unsigned Bs[BK][128 + 8];

    const int tid = threadIdx.x;
    const int m0 = blockIdx.y * 128;
    const int n0 = blockIdx.x * 128;

    const int w    = tid >> 5;
    const int lane = tid & 31;
    const int wr   = w & 1;         // BM/WM = 2
    const int wc   = w >> 1;        // 0..3
    const int lg   = lane >> 2;
    const int lt   = lane & 3;

    // Per-thread staging coordinates (4 chunks each for A and B)
    const int ar  = tid >> 3;       // A row 0..127 (chunks add +... no: id-based)
    const int ac4 = tid & 7;        // A k-quad
    const int br  = tid >> 5;       // B k row base
    const int bc4 = tid & 31;       // B n-quad

    float4 av[4], bv[4];

    // ---- prologue: load + store tile 0 ----
#pragma unroll
    for (int i = 0; i < 4; i++) {
        const int id = tid + i * 256;
        const int r  = id >> 3;
        const int c4 = id & 7;
        av[i] = *(const float4*)(A + (size_t)(m0 + r) * Kd + c4 * 4);
        const int rb = id >> 5;
        const int cb = id & 31;
        bv[i] = *(const float4*)(B + (size_t)rb * Dc + n0 + cb * 4);
    }
#pragma unroll
    for (int i = 0; i < 4; i++) {
        const int id = tid + i * 256;
        const int r  = id >> 3;
        const int c4 = id & 7;
        As[c4 * 4 + 0][r] = f2tf(av[i].x);
        As[c4 * 4 + 1][r] = f2tf(av[i].y);
        As[c4 * 4 + 2][r] = f2tf(av[i].z);
        As[c4 * 4 + 3][r] = f2tf(av[i].w);
        const int rb = id >> 5;
        const int cb = id & 31;
        Bs[rb][cb * 4 + 0] = f2tf(bv[i].x);
        Bs[rb][cb * 4 + 1] = f2tf(bv[i].y);
        Bs[rb][cb * 4 + 2] = f2tf(bv[i].z);
        Bs[rb][cb * 4 + 3] = f2tf(bv[i].w);
    }
    __syncthreads();

    float acc[MI][NI][4];
#pragma unroll
    for (int mi = 0; mi < MI; mi++)
#pragma unroll
        for (int ni = 0; ni < NI; ni++)
#pragma unroll
            for (int r = 0; r < 4; r++) acc[mi][ni][r] = 0.f;

#pragma unroll 1
    for (int k0 = 0; k0 < Kd; k0 += BK) {
        const int kn = k0 + BK;
        // ---- prefetch next tile into registers (overlaps compute) ----
        if (kn < Kd) {
#pragma unroll
            for (int i = 0; i < 4; i++) {
                const int id = tid + i * 256;
                const int r  = id >> 3;
                const int c4 = id & 7;
                av[i] = *(const float4*)(A + (size_t)(m0 + r) * Kd + kn + c4 * 4);
                const int rb = id >> 5;
                const int cb = id & 31;
                bv[i] = *(const float4*)(B + (size_t)(kn + rb) * Dc + n0 + cb * 4);
            }
        }

        // ---- compute current tile from smem ----
#pragma unroll
        for (int kk = 0; kk < BK; kk += 8) {
            unsigned af[MI][4], bf[NI][2];
#pragma unroll
            for (int mi = 0; mi < MI; mi++) {
                const int rb = wr * 64 + mi * 16;
                af[mi][0] = As[kk + lt    ][rb + lg    ];
                af[mi][1] = As[kk + lt    ][rb + lg + 8];
                af[mi][2] = As[kk + lt + 4][rb + lg    ];
                af[mi][3] = As[kk + lt + 4][rb + lg + 8];
            }
#pragma unroll
            for (int ni = 0; ni < NI; ni++) {
                const int nb = wc * 32 + ni * 8;
                bf[ni][0] = Bs[kk + lt    ][nb + lg];
                bf[ni][1] = Bs[kk + lt + 4][nb + lg];
            }
#pragma unroll
            for (int mi = 0; mi < MI; mi++)
#pragma unroll
                for (int ni = 0; ni < NI; ni++)
                    mma8(acc[mi][ni], af[mi], bf[ni]);
        }
        __syncthreads();

        // ---- commit prefetched tile to smem ----
        if (kn < Kd) {
#pragma unroll
            for (int i = 0; i < 4; i++) {
                const int id = tid + i * 256;
                const int r  = id >> 3;
                const int c4 = id & 7;
                As[c4 * 4 + 0][r] = f2tf(av[i].x);
                As[c4 * 4 + 1][r] = f2tf(av[i].y);
                As[c4 * 4 + 2][r] = f2tf(av[i].z);
                As[c4 * 4 + 3][r] = f2tf(av[i].w);
                const int rb = id >> 5;
                const int cb = id & 31;
                Bs[rb][cb * 4 + 0] = f2tf(bv[i].x);
                Bs[rb][cb * 4 + 1] = f2tf(bv[i].y);
                Bs[rb][cb * 4 + 2] = f2tf(bv[i].z);
                Bs[rb][cb * 4 + 3] = f2tf(bv[i].w);
            }
            __syncthreads();
        }
    }

    (void)ar; (void)ac4; (void)br; (void)bc4;

#pragma unroll
    for (int mi = 0; mi < MI; mi++) {
#pragma unroll
        for (int ni = 0; ni < NI; ni++) {
            const int gmb = m0 + wr * 64 + mi * 16 + lg;
            const int gn  = n0 + wc * 32 + ni * 8 + lt * 2;
#pragma unroll
            for (int hh = 0; hh < 2; hh++) {
                const int gm = gmb + hh * 8;
                const float v0 = acc[mi][ni][hh * 2 + 0];
                const float v1 = acc[mi][ni][hh * 2 + 1];
                if (EPI == 0) {
                    *(float2*)&C[(size_t)gm * Dc + gn] =
                        make_float2(v0 + bias[gn], v1 + bias[gn + 1]);
                } else {
                    float2 r = make_float2((v0 + bias[gn]) * scale,
                                           (v1 + bias[gn + 1]) * scale);
                    const int b = gm >> 11, s = gm & 2047;
                    const int hd = gn & 63, hq = gn >> 6;
                    *(float2*)&C[(((size_t)(b * Hc + hq) * Sc) + s) * HDc + hd] = r;
                }
            }
        }
    }
}

// ---------------------------------------------------------------------------
// Fused tensor-core flash attention (tf32 MMA, fp32 accum).  [R4 version:
// 128 regs -> 2 CTAs/SM; do NOT add registers here.]
// Block: one (b,h), 128 queries; 8 warps x 16 rows. Key tiles of 64.
// ---------------------------------------------------------------------------
__global__ __launch_bounds__(256)
void fattn(const float* __restrict__ Q, const float* __restrict__ K,
           const float* __restrict__ V, const float* __restrict__ mask,
           float* __restrict__ Octx)
{
    __shared__ unsigned Ks[64][72];   // [hd][key] tf32
    __shared__ unsigned Vs[64][72];   // [key][hd] tf32
    __shared__ float    Msk[64];

    const int tid  = threadIdx.x;
    const int w    = tid >> 5;
    const int lane = tid & 31;
    const int lg   = lane >> 2;
    const int lt   = lane & 3;

    const int bh = blockIdx.y;
    const int b  = bh >> 4;
    const int h  = bh & 15;
    const int q0 = blockIdx.x * 128 + w * 16;

    // Q fragments (one-time gmem gather, rows q0+lg / q0+lg+8)
    const float* Qb = Q + ((size_t)bh * Sc + q0) * HDc;
    unsigned qf[8][4];
#pragma unroll
    for (int kf = 0; kf < 8; kf++) {
        qf[kf][0] = f2tf(__ldg(Qb + (size_t)(lg    ) * HDc + kf * 8 + lt    ));
        qf[kf][1] = f2tf(__ldg(Qb + (size_t)(lg + 8) * HDc + kf * 8 + lt    ));
        qf[kf][2] = f2tf(__ldg(Qb + (size_t)(lg    ) * HDc + kf * 8 + lt + 4));
        qf[kf][3] = f2tf(__ldg(Qb + (size_t)(lg + 8) * HDc + kf * 8 + lt + 4));
    }

    float acc_o[8][4];
#pragma unroll
    for (int no = 0; no < 8; no++)
#pragma unroll
        for (int r = 0; r < 4; r++) acc_o[no][r] = 0.f;
    float m_lo = -1e30f, m_hi = -1e30f, l_lo = 0.f, l_hi = 0.f;

    const float* Kb = K + (size_t)bh * Sc * HDc;
    const float* Vb = V + (size_t)bh * Sc * HDc;
    const float* Mb = mask + (size_t)b * Sc;

    for (int kt = 0; kt < Sc; kt += 64) {
        // ---- stage mask + K (transposed) + V (natural) tiles ----
        if (tid < 64) Msk[tid] = Mb[kt + tid];
#pragma unroll
        for (int i = 0; i < 4; i++) {
            const int idx = tid + i * 256;          // 0..1023
            {
                const int key = idx & 63;
                const int h4  = idx >> 6;           // 0..15
                float4 kv = *(const float4*)(Kb + (size_t)(kt + key) * HDc + h4 * 4);
                Ks[h4 * 4 + 0][key] = f2tf(kv.x);
                Ks[h4 * 4 + 1][key] = f2tf(kv.y);
                Ks[h4 * 4 + 2][key] = f2tf(kv.z);
                Ks[h4 * 4 + 3][key] = f2tf(kv.w);
            }
            {
                const int key = idx >> 4;           // 0..63
                const int h4  = idx & 15;
                float4 vv = *(const float4*)(Vb + (size_t)(kt + key) * HDc + h4 * 4);
                *(uint4*)&Vs[key][h4 * 4] =
                    make_uint4(f2tf(vv.x), f2tf(vv.y), f2tf(vv.z), f2tf(vv.w));
            }
        }
        __syncthreads();

        // ---- S = Q K^T (16 rows x 64 keys per warp) ----
        float sc[8][4];
#pragma unroll
        for (int ni = 0; ni < 8; ni++)
#pragma unroll
            for (int r = 0; r < 4; r++) sc[ni][r] = 0.f;
#pragma unroll
        for (int kf = 0; kf < 8; kf++) {
#pragma unroll
            for (int ni = 0; ni < 8; ni++) {
                unsigned bf[2];
                bf[0] = Ks[kf * 8 + lt    ][ni * 8 + lg];
                bf[1] = Ks[kf * 8 + lt + 4][ni * 8 + lg];
                mma8(sc[ni], qf[kf], bf);
            }
        }

        // ---- mask + online softmax (quad-local) ----
        float rmax_lo = -1e30f, rmax_hi = -1e30f;
#pragma unroll
        for (int ni = 0; ni < 8; ni++) {
            const float mk0 = Msk[ni * 8 + 2 * lt];
            const float mk1 = Msk[ni * 8 + 2 * lt + 1];
            sc[ni][0] += mk0; sc[ni][1] += mk1;
            sc[ni][2] += mk0; sc[ni][3] += mk1;
            rmax_lo = fmaxf(rmax_lo, fmaxf(sc[ni][0], sc[ni][1]));
            rmax_hi = fmaxf(rmax_hi, fmaxf(sc[ni][2], sc[ni][3]));
        }
        rmax_lo = fmaxf(rmax_lo, __shfl_xor_sync(0xffffffffu, rmax_lo, 1));
        rmax_lo = fmaxf(rmax_lo, __shfl_xor_sync(0xffffffffu, rmax_lo, 2));
        rmax_hi = fmaxf(rmax_hi, __shfl_xor_sync(0xffffffffu, rmax_hi, 1));
        rmax_hi = fmaxf(rmax_hi, __shfl_xor_sync(0xffffffffu, rmax_hi, 2));

        const float mn_lo = fmaxf(m_lo, rmax_lo);
        const float mn_hi = fmaxf(m_hi, rmax_hi);
        const float al_lo = __expf(m_lo - mn_lo);
        const float al_hi = __expf(m_hi - mn_hi);
        m_lo = mn_lo; m_hi = mn_hi;

        float ps_lo = 0.f, ps_hi = 0.f;
#pragma unroll
        for (int ni = 0; ni < 8; ni++) {
            sc[ni][0] = __expf(sc[ni][0] - m_lo);
            sc[ni][1] = __expf(sc[ni][1] - m_lo);
            sc[ni][2] = __expf(sc[ni][2] - m_hi);
            sc[ni][3] = __expf(sc[ni][3] - m_hi);
            ps_lo += sc[ni][0] + sc[ni][1];
            ps_hi += sc[ni][2] + sc[ni][3];
        }
        l_lo = l_lo * al_lo + ps_lo;
        l_hi = l_hi * al_hi + ps_hi;
#pragma unroll
        for (int no = 0; no < 8; no++) {
            acc_o[no][0] *= al_lo; acc_o[no][1] *= al_lo;
            acc_o[no][2] *= al_hi; acc_o[no][3] *= al_hi;
        }

        // ---- PV: convert P C-frag -> A-frag via shuffles, then MMA ----
        const int src_lo = (lane & 28) | (lt >> 1);
        const int src_hi = src_lo + 2;
#pragma unroll
        for (int kf = 0; kf < 8; kf++) {
            unsigned a[4];
            {
                float v0 = __shfl_sync(0xffffffffu, sc[kf][0], src_lo);
                float v1 = __shfl_sync(0xffffffffu, sc[kf][1], src_lo);
                a[0] = f2tf((lt & 1) ? v1 : v0);
                float v2 = __shfl_sync(0xffffffffu, sc[kf][2], src_lo);
                float v3 = __shfl_sync(0xffffffffu, sc[kf][3], src_lo);
                a[1] = f2tf((lt & 1) ? v3 : v2);
                float u0 = __shfl_sync(0xffffffffu, sc[kf][0], src_hi);
                float u1 = __shfl_sync(0xffffffffu, sc[kf][1], src_hi);
                a[2] = f2tf((lt & 1) ? u1 : u0);
                float u2 = __shfl_sync(0xffffffffu, sc[kf][2], src_hi);
                float u3 = __shfl_sync(0xffffffffu, sc[kf][3], src_hi);
                a[3] = f2tf((lt & 1) ? u3 : u2);
            }
#pragma unroll
            for (int no = 0; no < 8; no++) {
                unsigned bf[2];
                bf[0] = Vs[kf * 8 + lt    ][no * 8 + lg];
                bf[1] = Vs[kf * 8 + lt + 4][no * 8 + lg];
                mma8(acc_o[no], a, bf);
            }
        }
        __syncthreads();
    }

    // ---- finalize: normalize and write ctx [B,S,D] ----
    l_lo += __shfl_xor_sync(0xffffffffu, l_lo, 1);
    l_lo += __shfl_xor_sync(0xffffffffu, l_lo, 2);
    l_hi += __shfl_xor_sync(0xffffffffu, l_hi, 1);
    l_hi += __shfl_xor_sync(0xffffffffu, l_hi, 2);
    const float inv_lo = 1.f / l_lo;
    const float inv_hi = 1.f / l_hi;

    float* Ob = Octx + ((size_t)b * Sc + q0) * Dc + h * HDc;
#pragma unroll
    for (int no = 0; no < 8; no++) {
        const int col = no * 8 + 2 * lt;
        *(float2*)(Ob + (size_t)(lg    ) * Dc + col) =
            make_float2(acc_o[no][0] * inv_lo, acc_o[no][1] * inv_lo);
        *(float2*)(Ob + (size_t)(lg + 8) * Dc + col) =
            make_float2(acc_o[no][2] * inv_hi, acc_o[no][3] * inv_hi);
    }
}

// ---------------------------------------------------------------------------
extern "C" void kernel_launch(void* const* d_in, const int* in_sizes, int n_in,
                              void* d_out, int out_size)
{
    const float* x    = (const float*)d_in[0];
    const float* mask = (const float*)d_in[1];
    const float* Wq   = (const float*)d_in[2];
    const float* bq   = (const float*)d_in[3];
    const float* Wk   = (const float*)d_in[4];
    const float* bk   = (const float*)d_in[5];
    const float* Wv   = (const float*)d_in[6];
    const float* bv   = (const float*)d_in[7];
    const float* Wo   = (const float*)d_in[8];
    const float* bo   = (const float*)d_in[9];
    float* out = (float*)d_out;

    void *qv, *kv, *vv, *cv;
    cudaGetSymbolAddress(&qv, g_q);
    cudaGetSymbolAddress(&kv, g_k);
    cudaGetSymbolAddress(&vv, g_v);
    cudaGetSymbolAddress(&cv, g_ctx);
    float* q   = (float*)qv;
    float* k   = (float*)kv;
    float* v   = (float*)vv;
    float* ctx = (float*)cv;

    dim3 g1(Dc / 128, Mtot / 128);   // (8, 32)
    mma_gemm<1><<<g1, 256>>>(x, Wq, bq, q, 0.125f);   // 1/sqrt(64)
    mma_gemm<1><<<g1, 256>>>(x, Wk, bk, k, 1.0f);
    mma_gemm<1><<<g1, 256>>>(x, Wv, bv, v, 1.0f);

    fattn<<<dim3(Sc / 128, Bc * Hc), 256>>>(q, k, v, mask, ctx);

    mma_gemm<0><<<g1, 256>>>(ctx, Wo, bo, out, 1.0f);
}

// round 7
// speedup vs baseline: 1.3946x; 1.1161x over previous
#include <cuda_runtime.h>
#include <math.h>

static constexpr int Bc  = 2;
static constexpr int Sc  = 2048;
static constexpr int Dc  = 1024;
static constexpr int Hc  = 16;
static constexpr int HDc = 64;
static constexpr int Mtot = Bc * Sc;   // 4096

// Scratch (device globals: allocation-free rule). ~67MB total.
// q/k/v hold tf32-rounded bit patterns (stored as float).
__device__ float g_q[(size_t)Bc * Hc * Sc * HDc];      // [B,H,S,HD]
__device__ float g_k[(size_t)Bc * Hc * Sc * HDc];
__device__ float g_v[(size_t)Bc * Hc * Sc * HDc];
__device__ float g_ctx[(size_t)Bc * Sc * Dc];          // [B,S,D]

// ---------------------------------------------------------------------------
// tf32 helpers
// ---------------------------------------------------------------------------
__device__ __forceinline__ unsigned f2tf(float x) {
    unsigned r;
    asm("cvt.rna.tf32.f32 %0, %1;" : "=r"(r) : "f"(x));
    return r;
}

__device__ __forceinline__ void mma8(float c[4], const unsigned a[4], const unsigned b[2]) {
    asm volatile(
        "mma.sync.aligned.m16n8k8.row.col.f32.tf32.tf32.f32 "
        "{%0,%1,%2,%3}, {%4,%5,%6,%7}, {%8,%9}, {%0,%1,%2,%3};"
        : "+f"(c[0]), "+f"(c[1]), "+f"(c[2]), "+f"(c[3])
        : "r"(a[0]), "r"(a[1]), "r"(a[2]), "r"(a[3]), "r"(b[0]), "r"(b[1]));
}

__device__ __forceinline__ void cpasync16(unsigned dst, const void* src) {
    asm volatile("cp.async.ca.shared.global [%0], [%1], 16;" :: "r"(dst), "l"(src));
}

// ---------------------------------------------------------------------------
// tf32 MMA GEMM (projections): C = A[M,K] @ B[K,N] + bias
// Register-prefetch pipeline (R6 version, known-good).
// EPI 0: row-major C = acc + bias (fp32).
// EPI 1: permuted [B,H,S,HD] <- tf32_rna((acc + bias) * scale)  [bits as float]
// ---------------------------------------------------------------------------
template <int EPI>
__global__ __launch_bounds__(256)
void mma_gemm(const float* __restrict__ A, const float* __restrict__ B,
              const float* __restrict__ bias, float* __restrict__ C,
              float scale)
{
    constexpr int BK = 32;
    constexpr int MI = 4, NI = 4;   // WM=64, WN=32
    constexpr int Kd = 1024;

    __shared__ unsigned As[BK][128 + 8];
    __shared__ unsigned Bs[BK][128 + 8];

    const int tid = threadIdx.x;
    const int m0 = blockIdx.y * 128;
    const int n0 = blockIdx.x * 128;

    const int w    = tid >> 5;
    const int lane = tid & 31;
    const int wr   = w & 1;
    const int wc   = w >> 1;
    const int lg   = lane >> 2;
    const int lt   = lane & 3;

    float4 av[4], bv[4];

    // ---- prologue: load + store tile 0 ----
#pragma unroll
    for (int i = 0; i < 4; i++) {
        const int id = tid + i * 256;
        const int r  = id >> 3;
        const int c4 = id & 7;
        av[i] = *(const float4*)(A + (size_t)(m0 + r) * Kd + c4 * 4);
        const int rb = id >> 5;
        const int cb = id & 31;
        bv[i] = *(const float4*)(B + (size_t)rb * Dc + n0 + cb * 4);
    }
#pragma unroll
    for (int i = 0; i < 4; i++) {
        const int id = tid + i * 256;
        const int r  = id >> 3;
        const int c4 = id & 7;
        As[c4 * 4 + 0][r] = f2tf(av[i].x);
        As[c4 * 4 + 1][r] = f2tf(av[i].y);
        As[c4 * 4 + 2][r] = f2tf(av[i].z);
        As[c4 * 4 + 3][r] = f2tf(av[i].w);
        const int rb = id >> 5;
        const int cb = id & 31;
        Bs[rb][cb * 4 + 0] = f2tf(bv[i].x);
        Bs[rb][cb * 4 + 1] = f2tf(bv[i].y);
        Bs[rb][cb * 4 + 2] = f2tf(bv[i].z);
        Bs[rb][cb * 4 + 3] = f2tf(bv[i].w);
    }
    __syncthreads();

    float acc[MI][NI][4];
#pragma unroll
    for (int mi = 0; mi < MI; mi++)
#pragma unroll
        for (int ni = 0; ni < NI; ni++)
#pragma unroll
            for (int r = 0; r < 4; r++) acc[mi][ni][r] = 0.f;

#pragma unroll 1
    for (int k0 = 0; k0 < Kd; k0 += BK) {
        const int kn = k0 + BK;
        if (kn < Kd) {
#pragma unroll
            for (int i = 0; i < 4; i++) {
                const int id = tid + i * 256;
                const int r  = id >> 3;
                const int c4 = id & 7;
                av[i] = *(const float4*)(A + (size_t)(m0 + r) * Kd + kn + c4 * 4);
                const int rb = id >> 5;
                const int cb = id & 31;
                bv[i] = *(const float4*)(B + (size_t)(kn + rb) * Dc + n0 + cb * 4);
            }
        }

#pragma unroll
        for (int kk = 0; kk < BK; kk += 8) {
            unsigned af[MI][4], bf[NI][2];
#pragma unroll
            for (int mi = 0; mi < MI; mi++) {
                const int rb = wr * 64 + mi * 16;
                af[mi][0] = As[kk + lt    ][rb + lg    ];
                af[mi][1] = As[kk + lt    ][rb + lg + 8];
                af[mi][2] = As[kk + lt + 4][rb + lg    ];
                af[mi][3] = As[kk + lt + 4][rb + lg + 8];
            }
#pragma unroll
            for (int ni = 0; ni < NI; ni++) {
                const int nb = wc * 32 + ni * 8;
                bf[ni][0] = Bs[kk + lt    ][nb + lg];
                bf[ni][1] = Bs[kk + lt + 4][nb + lg];
            }
#pragma unroll
            for (int mi = 0; mi < MI; mi++)
#pragma unroll
                for (int ni = 0; ni < NI; ni++)
                    mma8(acc[mi][ni], af[mi], bf[ni]);
        }
        __syncthreads();

        if (kn < Kd) {
#pragma unroll
            for (int i = 0; i < 4; i++) {
                const int id = tid + i * 256;
                const int r  = id >> 3;
                const int c4 = id & 7;
                As[c4 * 4 + 0][r] = f2tf(av[i].x);
                As[c4 * 4 + 1][r] = f2tf(av[i].y);
                As[c4 * 4 + 2][r] = f2tf(av[i].z);
                As[c4 * 4 + 3][r] = f2tf(av[i].w);
                const int rb = id >> 5;
                const int cb = id & 31;
                Bs[rb][cb * 4 + 0] = f2tf(bv[i].x);
                Bs[rb][cb * 4 + 1] = f2tf(bv[i].y);
                Bs[rb][cb * 4 + 2] = f2tf(bv[i].z);
                Bs[rb][cb * 4 + 3] = f2tf(bv[i].w);
            }
            __syncthreads();
        }
    }

#pragma unroll
    for (int mi = 0; mi < MI; mi++) {
#pragma unroll
        for (int ni = 0; ni < NI; ni++) {
            const int gmb = m0 + wr * 64 + mi * 16 + lg;
            const int gn  = n0 + wc * 32 + ni * 8 + lt * 2;
#pragma unroll
            for (int hh = 0; hh < 2; hh++) {
                const int gm = gmb + hh * 8;
                const float v0 = acc[mi][ni][hh * 2 + 0];
                const float v1 = acc[mi][ni][hh * 2 + 1];
                if (EPI == 0) {
                    *(float2*)&C[(size_t)gm * Dc + gn] =
                        make_float2(v0 + bias[gn], v1 + bias[gn + 1]);
                } else {
                    // store tf32-rounded bits so fattn needs no conversion
                    float2 r;
                    r.x = __uint_as_float(f2tf((v0 + bias[gn])     * scale));
                    r.y = __uint_as_float(f2tf((v1 + bias[gn + 1]) * scale));
                    const int b = gm >> 11, s = gm & 2047;
                    const int hd = gn & 63, hq = gn >> 6;
                    *(float2*)&C[(((size_t)(b * Hc + hq) * Sc) + s) * HDc + hd] = r;
                }
            }
        }
    }
}

// ---------------------------------------------------------------------------
// Fused tensor-core flash attention, cp.async double-buffered.
// Block: one (b,h), 128 queries; 8 warps x 16 rows. Key tiles of 32, 2 stages.
// K smem [key][68] (banks 4*lg+lt), V smem [key][72] (banks 8*lt+lg):
// conflict-free fragment LDS, cp.async-friendly natural layout (q/k/v are
// pre-converted tf32 bits). Softmax warp-local; P conv via register shuffles.
// ---------------------------------------------------------------------------
__global__ __launch_bounds__(256)
void fattn(const float* __restrict__ Q, const float* __restrict__ K,
           const float* __restrict__ V, const float* __restrict__ mask,
           float* __restrict__ Octx)
{
    constexpr int TK   = 32;    // keys per tile
    constexpr int KST  = 68;    // K row stride (floats)
    constexpr int VST  = 72;    // V row stride (floats)

    __shared__ __align__(16) float Ksm[2][TK * KST];
    __shared__ __align__(16) float Vsm[2][TK * VST];
    __shared__ __align__(16) float Msm[2][TK];

    const int tid  = threadIdx.x;
    const int w    = tid >> 5;
    const int lane = tid & 31;
    const int lg   = lane >> 2;
    const int lt   = lane & 3;

    const int bh = blockIdx.y;
    const int b  = bh >> 4;
    const int h  = bh & 15;
    const int q0 = blockIdx.x * 128 + w * 16;

    const float* Kb = K + (size_t)bh * Sc * HDc;
    const float* Vb = V + (size_t)bh * Sc * HDc;
    const float* Mb = mask + (size_t)b * Sc;

    const unsigned kbase = (unsigned)__cvta_generic_to_shared(&Ksm[0][0]);
    const unsigned vbase = (unsigned)__cvta_generic_to_shared(&Vsm[0][0]);
    const unsigned mbase = (unsigned)__cvta_generic_to_shared(&Msm[0][0]);

    // Q fragments (values already tf32 bits)
    const float* Qb = Q + ((size_t)bh * Sc + q0) * HDc;
    unsigned qf[8][4];
#pragma unroll
    for (int kf = 0; kf < 8; kf++) {
        qf[kf][0] = __float_as_uint(__ldg(Qb + (size_t)(lg    ) * HDc + kf * 8 + lt    ));
        qf[kf][1] = __float_as_uint(__ldg(Qb + (size_t)(lg + 8) * HDc + kf * 8 + lt    ));
        qf[kf][2] = __float_as_uint(__ldg(Qb + (size_t)(lg    ) * HDc + kf * 8 + lt + 4));
        qf[kf][3] = __float_as_uint(__ldg(Qb + (size_t)(lg + 8) * HDc + kf * 8 + lt + 4));
    }

    float acc_o[8][4];
#pragma unroll
    for (int no = 0; no < 8; no++)
#pragma unroll
        for (int r = 0; r < 4; r++) acc_o[no][r] = 0.f;
    float m_lo = -1e30f, m_hi = -1e30f, l_lo = 0.f, l_hi = 0.f;

    // ---- staging: cp.async one 32-key tile into buffer `buf` ----
    auto stage = [&](int buf, int kt) {
#pragma unroll
        for (int i = 0; i < 2; i++) {
            const int id  = tid + i * 256;   // 0..511
            const int key = id >> 4;         // 0..31
            const int c4  = id & 15;         // 16B chunk
            cpasync16(kbase + (unsigned)(buf * TK * KST + key * KST + c4 * 4) * 4,
                      Kb + (size_t)(kt + key) * HDc + c4 * 4);
            cpasync16(vbase + (unsigned)(buf * TK * VST + key * VST + c4 * 4) * 4,
                      Vb + (size_t)(kt + key) * HDc + c4 * 4);
        }
        if (tid < 8)
            cpasync16(mbase + (unsigned)(buf * TK + tid * 4) * 4, Mb + kt + tid * 4);
    };

    // prologue: stage tile 0
    stage(0, 0);
    asm volatile("cp.async.commit_group;");

    constexpr int NT = Sc / TK;   // 64
#pragma unroll 1
    for (int it = 0; it < NT; it++) {
        const int cur = it & 1;
        if (it + 1 < NT) stage((it + 1) & 1, (it + 1) * TK);
        asm volatile("cp.async.commit_group;");
        asm volatile("cp.async.wait_group 1;");
        __syncthreads();

        const float* Kc = Ksm[cur];
        const float* Vc = Vsm[cur];
        const float* Mc = Msm[cur];

        // ---- S = Q K^T (16 rows x 32 keys per warp) ----
        float sc[4][4];
#pragma unroll
        for (int ni = 0; ni < 4; ni++)
#pragma unroll
            for (int r = 0; r < 4; r++) sc[ni][r] = 0.f;
#pragma unroll
        for (int kf = 0; kf < 8; kf++) {
#pragma unroll
            for (int ni = 0; ni < 4; ni++) {
                const int row = (ni * 8 + lg) * KST + kf * 8 + lt;
                unsigned bf[2];
                bf[0] = __float_as_uint(Kc[row]);
                bf[1] = __float_as_uint(Kc[row + 4]);
                mma8(sc[ni], qf[kf], bf);
            }
        }

        // ---- mask + online softmax (quad-local) ----
        float rmax_lo = -1e30f, rmax_hi = -1e30f;
#pragma unroll
        for (int ni = 0; ni < 4; ni++) {
            const float mk0 = Mc[ni * 8 + 2 * lt];
            const float mk1 = Mc[ni * 8 + 2 * lt + 1];
            sc[ni][0] += mk0; sc[ni][1] += mk1;
            sc[ni][2] += mk0; sc[ni][3] += mk1;
            rmax_lo = fmaxf(rmax_lo, fmaxf(sc[ni][0], sc[ni][1]));
            rmax_hi = fmaxf(rmax_hi, fmaxf(sc[ni][2], sc[ni][3]));
        }
        rmax_lo = fmaxf(rmax_lo, __shfl_xor_sync(0xffffffffu, rmax_lo, 1));
        rmax_lo = fmaxf(rmax_lo, __shfl_xor_sync(0xffffffffu, rmax_lo, 2));
        rmax_hi = fmaxf(rmax_hi, __shfl_xor_sync(0xffffffffu, rmax_hi, 1));
        rmax_hi = fmaxf(rmax_hi, __shfl_xor_sync(0xffffffffu, rmax_hi, 2));

        const float mn_lo = fmaxf(m_lo, rmax_lo);
        const float mn_hi = fmaxf(m_hi, rmax_hi);
        const float al_lo = __expf(m_lo - mn_lo);
        const float al_hi = __expf(m_hi - mn_hi);
        m_lo = mn_lo; m_hi = mn_hi;

        float ps_lo = 0.f, ps_hi = 0.f;
#pragma unroll
        for (int ni = 0; ni < 4; ni++) {
            sc[ni][0] = __expf(sc[ni][0] - m_lo);
            sc[ni][1] = __expf(sc[ni][1] - m_lo);
            sc[ni][2] = __expf(sc[ni][2] - m_hi);
            sc[ni][3] = __expf(sc[ni][3] - m_hi);
            ps_lo += sc[ni][0] + sc[ni][1];
            ps_hi += sc[ni][2] + sc[ni][3];
        }
        l_lo = l_lo * al_lo + ps_lo;
        l_hi = l_hi * al_hi + ps_hi;
#pragma unroll
        for (int no = 0; no < 8; no++) {
            acc_o[no][0] *= al_lo; acc_o[no][1] *= al_lo;
            acc_o[no][2] *= al_hi; acc_o[no][3] *= al_hi;
        }

        // ---- PV: convert P C-frag -> A-frag via shuffles, then MMA ----
        const int src_lo = (lane & 28) | (lt >> 1);
        const int src_hi = src_lo + 2;
#pragma unroll
        for (int kf = 0; kf < 4; kf++) {
            unsigned a[4];
            {
                float v0 = __shfl_sync(0xffffffffu, sc[kf][0], src_lo);
                float v1 = __shfl_sync(0xffffffffu, sc[kf][1], src_lo);
                a[0] = f2tf((lt & 1) ? v1 : v0);
                float v2 = __shfl_sync(0xffffffffu, sc[kf][2], src_lo);
                float v3 = __shfl_sync(0xffffffffu, sc[kf][3], src_lo);
                a[1] = f2tf((lt & 1) ? v3 : v2);
                float u0 = __shfl_sync(0xffffffffu, sc[kf][0], src_hi);
                float u1 = __shfl_sync(0xffffffffu, sc[kf][1], src_hi);
                a[2] = f2tf((lt & 1) ? u1 : u0);
                float u2 = __shfl_sync(0xffffffffu, sc[kf][2], src_hi);
                float u3 = __shfl_sync(0xffffffffu, sc[kf][3], src_hi);
                a[3] = f2tf((lt & 1) ? u3 : u2);
            }
            const int rbase = (kf * 8 + lt) * VST;
#pragma unroll
            for (int no = 0; no < 8; no++) {
                unsigned bf[2];
                bf[0] = __float_as_uint(Vc[rbase            + no * 8 + lg]);
                bf[1] = __float_as_uint(Vc[rbase + 4 * VST  + no * 8 + lg]);
                mma8(acc_o[no], a, bf);
            }
        }
        __syncthreads();
    }

    // ---- finalize: normalize and write ctx [B,S,D] ----
    l_lo += __shfl_xor_sync(0xffffffffu, l_lo, 1);
    l_lo += __shfl_xor_sync(0xffffffffu, l_lo, 2);
    l_hi += __shfl_xor_sync(0xffffffffu, l_hi, 1);
    l_hi += __shfl_xor_sync(0xffffffffu, l_hi, 2);
    const float inv_lo = 1.f / l_lo;
    const float inv_hi = 1.f / l_hi;

    float* Ob = Octx + ((size_t)b * Sc + q0) * Dc + h * HDc;
#pragma unroll
    for (int no = 0; no < 8; no++) {
        const int col = no * 8 + 2 * lt;
        *(float2*)(Ob + (size_t)(lg    ) * Dc + col) =
            make_float2(acc_o[no][0] * inv_lo, acc_o[no][1] * inv_lo);
        *(float2*)(Ob + (size_t)(lg + 8) * Dc + col) =
            make_float2(acc_o[no][2] * inv_hi, acc_o[no][3] * inv_hi);
    }
}

// ---------------------------------------------------------------------------
extern "C" void kernel_launch(void* const* d_in, const int* in_sizes, int n_in,
                              void* d_out, int out_size)
{
    const float* x    = (const float*)d_in[0];
    const float* mask = (const float*)d_in[1];
    const float* Wq   = (const float*)d_in[2];
    const float* bq   = (const float*)d_in[3];
    const float* Wk   = (const float*)d_in[4];
    const float* bk   = (const float*)d_in[5];
    const float* Wv   = (const float*)d_in[6];
    const float* bv   = (const float*)d_in[7];
    const float* Wo   = (const float*)d_in[8];
    const float* bo   = (const float*)d_in[9];
    float* out = (float*)d_out;

    void *qv, *kv, *vv, *cv;
    cudaGetSymbolAddress(&qv, g_q);
    cudaGetSymbolAddress(&kv, g_k);
    cudaGetSymbolAddress(&vv, g_v);
    cudaGetSymbolAddress(&cv, g_ctx);
    float* q   = (float*)qv;
    float* k   = (float*)kv;
    float* v   = (float*)vv;
    float* ctx = (float*)cv;

    dim3 g1(Dc / 128, Mtot / 128);   // (8, 32)
    mma_gemm<1><<<g1, 256>>>(x, Wq, bq, q, 0.125f);   // 1/sqrt(64)
    mma_gemm<1><<<g1, 256>>>(x, Wk, bk, k, 1.0f);
    mma_gemm<1><<<g1, 256>>>(x, Wv, bv, v, 1.0f);

    fattn<<<dim3(Sc / 128, Bc * Hc), 256>>>(q, k, v, mask, ctx);

    mma_gemm<0><<<g1, 256>>>(ctx, Wo, bo, out, 1.0f);
}

// round 8
// speedup vs baseline: 1.5851x; 1.1366x over previous
#include <cuda_runtime.h>
#include <math.h>

static constexpr int Bc  = 2;
static constexpr int Sc  = 2048;
static constexpr int Dc  = 1024;
static constexpr int Hc  = 16;
static constexpr int HDc = 64;
static constexpr int Mtot = Bc * Sc;   // 4096

// Scratch (device globals: allocation-free rule). ~100MB total.
// All MMA operands live as tf32-rounded bit patterns (stored as float).
__device__ float g_q[(size_t)Bc * Hc * Sc * HDc];      // [B,H,S,HD] tf32 bits
__device__ float g_k[(size_t)Bc * Hc * Sc * HDc];
__device__ float g_v[(size_t)Bc * Hc * Sc * HDc];
__device__ float g_ctx[(size_t)Bc * Sc * Dc];          // [B,S,D]  tf32 bits
__device__ float g_xt[(size_t)Mtot * Dc];              // x  -> tf32 bits
__device__ float g_wq[(size_t)Dc * Dc];                // W  -> tf32 bits
__device__ float g_wk[(size_t)Dc * Dc];
__device__ float g_wv[(size_t)Dc * Dc];
__device__ float g_wo[(size_t)Dc * Dc];

// ---------------------------------------------------------------------------
// tf32 helpers
// ---------------------------------------------------------------------------
__device__ __forceinline__ unsigned f2tf(float x) {
    unsigned r;
    asm("cvt.rna.tf32.f32 %0, %1;" : "=r"(r) : "f"(x));
    return r;
}

__device__ __forceinline__ void mma8(float c[4], const unsigned a[4], const unsigned b[2]) {
    asm volatile(
        "mma.sync.aligned.m16n8k8.row.col.f32.tf32.tf32.f32 "
        "{%0,%1,%2,%3}, {%4,%5,%6,%7}, {%8,%9}, {%0,%1,%2,%3};"
        : "+f"(c[0]), "+f"(c[1]), "+f"(c[2]), "+f"(c[3])
        : "r"(a[0]), "r"(a[1]), "r"(a[2]), "r"(a[3]), "r"(b[0]), "r"(b[1]));
}

__device__ __forceinline__ void cpasync16(unsigned dst, const void* src) {
    asm volatile("cp.async.ca.shared.global [%0], [%1], 16;" :: "r"(dst), "l"(src));
}

// ---------------------------------------------------------------------------
// Elementwise tf32 pre-rounding: dst = bits(cvt.rna.tf32(src))
// ---------------------------------------------------------------------------
__global__ __launch_bounds__(256)
void tf32_convert(const float* __restrict__ src, float* __restrict__ dst, int n4)
{
    const int i = blockIdx.x * 256 + threadIdx.x;
    if (i < n4) {
        float4 v = ((const float4*)src)[i];
        float4 r;
        r.x = __uint_as_float(f2tf(v.x));
        r.y = __uint_as_float(f2tf(v.y));
        r.z = __uint_as_float(f2tf(v.z));
        r.w = __uint_as_float(f2tf(v.w));
        ((float4*)dst)[i] = r;
    }
}

// ---------------------------------------------------------------------------
// tf32 MMA GEMM (projections): C = A[M,K] @ B[K,N] + bias
// A, B hold tf32 bits. cp.async double-buffered, BK=16, no STS/cvt in loop.
// A smem [m][20]  (banks 20*lg+lt -> conflict-free fragment loads)
// B smem 4 x 32-col subtiles [k][40] (banks 8*lt+lg -> conflict-free)
// EPI 0: row-major C = acc + bias (fp32)
// EPI 1: permuted [B,H,S,HD] <- tf32 bits of (acc + bias) * scale
// 128x128x16 stage tile, warps 2x4 (WM=64, WN=32), 256 threads.
// ---------------------------------------------------------------------------
template <int EPI>
__global__ __launch_bounds__(256)
void mma_gemm(const float* __restrict__ A, const float* __restrict__ B,
              const float* __restrict__ bias, float* __restrict__ C,
              float scale)
{
    constexpr int MI = 4, NI = 4;
    constexpr int Kd = 1024;
    constexpr int ABUF = 128 * 20;      // 2560 floats
    constexpr int BBUF = 4 * 16 * 40;   // 2560 floats

    __shared__ __align__(16) float As[2][ABUF];
    __shared__ __align__(16) float Bs[2][BBUF];

    const int tid = threadIdx.x;
    const int m0 = blockIdx.y * 128;
    const int n0 = blockIdx.x * 128;

    const int w    = tid >> 5;
    const int lane = tid & 31;
    const int wr   = w & 1;
    const int wc   = w >> 1;
    const int lg   = lane >> 2;
    const int lt   = lane & 3;

    const unsigned abase = (unsigned)__cvta_generic_to_shared(&As[0][0]);
    const unsigned bbase = (unsigned)__cvta_generic_to_shared(&Bs[0][0]);

    auto stage = [&](int buf, int k0) {
#pragma unroll
        for (int i = 0; i < 2; i++) {
            const int c   = tid + i * 256;      // 0..511
            const int row = c >> 2;             // A row 0..127
            const int cq  = c & 3;              // 16B chunk in row
            cpasync16(abase + (unsigned)(buf * ABUF + row * 20 + cq * 4) * 4,
                      A + (size_t)(m0 + row) * Kd + k0 + cq * 4);
        }
#pragma unroll
        for (int i = 0; i < 2; i++) {
            const int c   = tid + i * 256;      // 0..511
            const int k   = c >> 5;             // 0..15
            const int g   = c & 31;             // 4-float group in 128-col row
            const int sub = g >> 3;             // 0..3
            const int npr = (g & 7) * 4;        // 0..28
            cpasync16(bbase + (unsigned)(buf * BBUF + sub * 640 + k * 40 + npr) * 4,
                      B + (size_t)(k0 + k) * Dc + n0 + g * 4);
        }
    };

    float acc[MI][NI][4];
#pragma unroll
    for (int mi = 0; mi < MI; mi++)
#pragma unroll
        for (int ni = 0; ni < NI; ni++)
#pragma unroll
            for (int r = 0; r < 4; r++) acc[mi][ni][r] = 0.f;

    stage(0, 0);
    asm volatile("cp.async.commit_group;");

    constexpr int NT = Kd / 16;   // 64
#pragma unroll 1
    for (int it = 0; it < NT; it++) {
        const int cur = it & 1;
        if (it + 1 < NT) stage((it + 1) & 1, (it + 1) * 16);
        asm volatile("cp.async.commit_group;");
        asm volatile("cp.async.wait_group 1;");
        __syncthreads();

        const float* Ac = As[cur];
        const float* Bsub = &Bs[cur][wc * 640];

#pragma unroll
        for (int kk = 0; kk < 16; kk += 8) {
            unsigned af[MI][4], bf[NI][2];
#pragma unroll
            for (int mi = 0; mi < MI; mi++) {
                const int rb = wr * 64 + mi * 16;
                af[mi][0] = __float_as_uint(Ac[(rb + lg    ) * 20 + kk + lt    ]);
                af[mi][1] = __float_as_uint(Ac[(rb + lg + 8) * 20 + kk + lt    ]);
                af[mi][2] = __float_as_uint(Ac[(rb + lg    ) * 20 + kk + lt + 4]);
                af[mi][3] = __float_as_uint(Ac[(rb + lg + 8) * 20 + kk + lt + 4]);
            }
#pragma unroll
            for (int ni = 0; ni < NI; ni++) {
                bf[ni][0] = __float_as_uint(Bsub[(kk + lt    ) * 40 + ni * 8 + lg]);
                bf[ni][1] = __float_as_uint(Bsub[(kk + lt + 4) * 40 + ni * 8 + lg]);
            }
#pragma unroll
            for (int mi = 0; mi < MI; mi++)
#pragma unroll
                for (int ni = 0; ni < NI; ni++)
                    mma8(acc[mi][ni], af[mi], bf[ni]);
        }
        __syncthreads();
    }

#pragma unroll
    for (int mi = 0; mi < MI; mi++) {
#pragma unroll
        for (int ni = 0; ni < NI; ni++) {
            const int gmb = m0 + wr * 64 + mi * 16 + lg;
            const int gn  = n0 + wc * 32 + ni * 8 + lt * 2;
#pragma unroll
            for (int hh = 0; hh < 2; hh++) {
                const int gm = gmb + hh * 8;
                const float v0 = acc[mi][ni][hh * 2 + 0];
                const float v1 = acc[mi][ni][hh * 2 + 1];
                if (EPI == 0) {
                    *(float2*)&C[(size_t)gm * Dc + gn] =
                        make_float2(v0 + bias[gn], v1 + bias[gn + 1]);
                } else {
                    float2 r;
                    r.x = __uint_as_float(f2tf((v0 + bias[gn])     * scale));
                    r.y = __uint_as_float(f2tf((v1 + bias[gn + 1]) * scale));
                    const int b = gm >> 11, s = gm & 2047;
                    const int hd = gn & 63, hq = gn >> 6;
                    *(float2*)&C[(((size_t)(b * Hc + hq) * Sc) + s) * HDc + hd] = r;
                }
            }
        }
    }
}

// ---------------------------------------------------------------------------
// Fused tensor-core flash attention, cp.async double-buffered (R7, known-good).
// Epilogue now writes ctx as tf32 bits (bit-identical downstream).
// ---------------------------------------------------------------------------
__global__ __launch_bounds__(256)
void fattn(const float* __restrict__ Q, const float* __restrict__ K,
           const float* __restrict__ V, const float* __restrict__ mask,
           float* __restrict__ Octx)
{
    constexpr int TK   = 32;
    constexpr int KST  = 68;
    constexpr int VST  = 72;

    __shared__ __align__(16) float Ksm[2][TK * KST];
    __shared__ __align__(16) float Vsm[2][TK * VST];
    __shared__ __align__(16) float Msm[2][TK];

    const int tid  = threadIdx.x;
    const int w    = tid >> 5;
    const int lane = tid & 31;
    const int lg   = lane >> 2;
    const int lt   = lane & 3;

    const int bh = blockIdx.y;
    const int b  = bh >> 4;
    const int h  = bh & 15;
    const int q0 = blockIdx.x * 128 + w * 16;

    const float* Kb = K + (size_t)bh * Sc * HDc;
    const float* Vb = V + (size_t)bh * Sc * HDc;
    const float* Mb = mask + (size_t)b * Sc;

    const unsigned kbase = (unsigned)__cvta_generic_to_shared(&Ksm[0][0]);
    const unsigned vbase = (unsigned)__cvta_generic_to_shared(&Vsm[0][0]);
    const unsigned mbase = (unsigned)__cvta_generic_to_shared(&Msm[0][0]);

    const float* Qb = Q + ((size_t)bh * Sc + q0) * HDc;
    unsigned qf[8][4];
#pragma unroll
    for (int kf = 0; kf < 8; kf++) {
        qf[kf][0] = __float_as_uint(__ldg(Qb + (size_t)(lg    ) * HDc + kf * 8 + lt    ));
        qf[kf][1] = __float_as_uint(__ldg(Qb + (size_t)(lg + 8) * HDc + kf * 8 + lt    ));
        qf[kf][2] = __float_as_uint(__ldg(Qb + (size_t)(lg    ) * HDc + kf * 8 + lt + 4));
        qf[kf][3] = __float_as_uint(__ldg(Qb + (size_t)(lg + 8) * HDc + kf * 8 + lt + 4));
    }

    float acc_o[8][4];
#pragma unroll
    for (int no = 0; no < 8; no++)
#pragma unroll
        for (int r = 0; r < 4; r++) acc_o[no][r] = 0.f;
    float m_lo = -1e30f, m_hi = -1e30f, l_lo = 0.f, l_hi = 0.f;

    auto stage = [&](int buf, int kt) {
#pragma unroll
        for (int i = 0; i < 2; i++) {
            const int id  = tid + i * 256;
            const int key = id >> 4;
            const int c4  = id & 15;
            cpasync16(kbase + (unsigned)(buf * TK * KST + key * KST + c4 * 4) * 4,
                      Kb + (size_t)(kt + key) * HDc + c4 * 4);
            cpasync16(vbase + (unsigned)(buf * TK * VST + key * VST + c4 * 4) * 4,
                      Vb + (size_t)(kt + key) * HDc + c4 * 4);
        }
        if (tid < 8)
            cpasync16(mbase + (unsigned)(buf * TK + tid * 4) * 4, Mb + kt + tid * 4);
    };

    stage(0, 0);
    asm volatile("cp.async.commit_group;");

    constexpr int NT = Sc / TK;   // 64
#pragma unroll 1
    for (int it = 0; it < NT; it++) {
        const int cur = it & 1;
        if (it + 1 < NT) stage((it + 1) & 1, (it + 1) * TK);
        asm volatile("cp.async.commit_group;");
        asm volatile("cp.async.wait_group 1;");
        __syncthreads();

        const float* Kc = Ksm[cur];
        const float* Vc = Vsm[cur];
        const float* Mc = Msm[cur];

        float sc[4][4];
#pragma unroll
        for (int ni = 0; ni < 4; ni++)
#pragma unroll
            for (int r = 0; r < 4; r++) sc[ni][r] = 0.f;
#pragma unroll
        for (int kf = 0; kf < 8; kf++) {
#pragma unroll
            for (int ni = 0; ni < 4; ni++) {
                const int row = (ni * 8 + lg) * KST + kf * 8 + lt;
                unsigned bf[2];
                bf[0] = __float_as_uint(Kc[row]);
                bf[1] = __float_as_uint(Kc[row + 4]);
                mma8(sc[ni], qf[kf], bf);
            }
        }

        float rmax_lo = -1e30f, rmax_hi = -1e30f;
#pragma unroll
        for (int ni = 0; ni < 4; ni++) {
            const float mk0 = Mc[ni * 8 + 2 * lt];
            const float mk1 = Mc[ni * 8 + 2 * lt + 1];
            sc[ni][0] += mk0; sc[ni][1] += mk1;
            sc[ni][2] += mk0; sc[ni][3] += mk1;
            rmax_lo = fmaxf(rmax_lo, fmaxf(sc[ni][0], sc[ni][1]));
            rmax_hi = fmaxf(rmax_hi, fmaxf(sc[ni][2], sc[ni][3]));
        }
        rmax_lo = fmaxf(rmax_lo, __shfl_xor_sync(0xffffffffu, rmax_lo, 1));
        rmax_lo = fmaxf(rmax_lo, __shfl_xor_sync(0xffffffffu, rmax_lo, 2));
        rmax_hi = fmaxf(rmax_hi, __shfl_xor_sync(0xffffffffu, rmax_hi, 1));
        rmax_hi = fmaxf(rmax_hi, __shfl_xor_sync(0xffffffffu, rmax_hi, 2));

        const float mn_lo = fmaxf(m_lo, rmax_lo);
        const float mn_hi = fmaxf(m_hi, rmax_hi);
        const float al_lo = __expf(m_lo - mn_lo);
        const float al_hi = __expf(m_hi - mn_hi);
        m_lo = mn_lo; m_hi = mn_hi;

        float ps_lo = 0.f, ps_hi = 0.f;
#pragma unroll
        for (int ni = 0; ni < 4; ni++) {
            sc[ni][0] = __expf(sc[ni][0] - m_lo);
            sc[ni][1] = __expf(sc[ni][1] - m_lo);
            sc[ni][2] = __expf(sc[ni][2] - m_hi);
            sc[ni][3] = __expf(sc[ni][3] - m_hi);
            ps_lo += sc[ni][0] + sc[ni][1];
            ps_hi += sc[ni][2] + sc[ni][3];
        }
        l_lo = l_lo * al_lo + ps_lo;
        l_hi = l_hi * al_hi + ps_hi;
#pragma unroll
        for (int no = 0; no < 8; no++) {
            acc_o[no][0] *= al_lo; acc_o[no][1] *= al_lo;
            acc_o[no][2] *= al_hi; acc_o[no][3] *= al_hi;
        }

        const int src_lo = (lane & 28) | (lt >> 1);
        const int src_hi = src_lo + 2;
#pragma unroll
        for (int kf = 0; kf < 4; kf++) {
            unsigned a[4];
            {
                float v0 = __shfl_sync(0xffffffffu, sc[kf][0], src_lo);
                float v1 = __shfl_sync(0xffffffffu, sc[kf][1], src_lo);
                a[0] = f2tf((lt & 1) ? v1 : v0);
                float v2 = __shfl_sync(0xffffffffu, sc[kf][2], src_lo);
                float v3 = __shfl_sync(0xffffffffu, sc[kf][3], src_lo);
                a[1] = f2tf((lt & 1) ? v3 : v2);
                float u0 = __shfl_sync(0xffffffffu, sc[kf][0], src_hi);
                float u1 = __shfl_sync(0xffffffffu, sc[kf][1], src_hi);
                a[2] = f2tf((lt & 1) ? u1 : u0);
                float u2 = __shfl_sync(0xffffffffu, sc[kf][2], src_hi);
                float u3 = __shfl_sync(0xffffffffu, sc[kf][3], src_hi);
                a[3] = f2tf((lt & 1) ? u3 : u2);
            }
            const int rbase = (kf * 8 + lt) * VST;
#pragma unroll
            for (int no = 0; no < 8; no++) {
                unsigned bf[2];
                bf[0] = __float_as_uint(Vc[rbase            + no * 8 + lg]);
                bf[1] = __float_as_uint(Vc[rbase + 4 * VST  + no * 8 + lg]);
                mma8(acc_o[no], a, bf);
            }
        }
        __syncthreads();
    }

    l_lo += __shfl_xor_sync(0xffffffffu, l_lo, 1);
    l_lo += __shfl_xor_sync(0xffffffffu, l_lo, 2);
    l_hi += __shfl_xor_sync(0xffffffffu, l_hi, 1);
    l_hi += __shfl_xor_sync(0xffffffffu, l_hi, 2);
    const float inv_lo = 1.f / l_lo;
    const float inv_hi = 1.f / l_hi;

    // write ctx as tf32 bits (consumed as GEMM A operand)
    float* Ob = Octx + ((size_t)b * Sc + q0) * Dc + h * HDc;
#pragma unroll
    for (int no = 0; no < 8; no++) {
        const int col = no * 8 + 2 * lt;
        float2 r0, r1;
        r0.x = __uint_as_float(f2tf(acc_o[no][0] * inv_lo));
        r0.y = __uint_as_float(f2tf(acc_o[no][1] * inv_lo));
        r1.x = __uint_as_float(f2tf(acc_o[no][2] * inv_hi));
        r1.y = __uint_as_float(f2tf(acc_o[no][3] * inv_hi));
        *(float2*)(Ob + (size_t)(lg    ) * Dc + col) = r0;
        *(float2*)(Ob + (size_t)(lg + 8) * Dc + col) = r1;
    }
}

// ---------------------------------------------------------------------------
extern "C" void kernel_launch(void* const* d_in, const int* in_sizes, int n_in,
                              void* d_out, int out_size)
{
    const float* x    = (const float*)d_in[0];
    const float* mask = (const float*)d_in[1];
    const float* Wq   = (const float*)d_in[2];
    const float* bq   = (const float*)d_in[3];
    const float* Wk   = (const float*)d_in[4];
    const float* bk   = (const float*)d_in[5];
    const float* Wv   = (const float*)d_in[6];
    const float* bv   = (const float*)d_in[7];
    const float* Wo   = (const float*)d_in[8];
    const float* bo   = (const float*)d_in[9];
    float* out = (float*)d_out;

    void *qv, *kv, *vv, *cv, *xtv, *wqv, *wkv, *wvv, *wov;
    cudaGetSymbolAddress(&qv,  g_q);
    cudaGetSymbolAddress(&kv,  g_k);
    cudaGetSymbolAddress(&vv,  g_v);
    cudaGetSymbolAddress(&cv,  g_ctx);
    cudaGetSymbolAddress(&xtv, g_xt);
    cudaGetSymbolAddress(&wqv, g_wq);
    cudaGetSymbolAddress(&wkv, g_wk);
    cudaGetSymbolAddress(&wvv, g_wv);
    cudaGetSymbolAddress(&wov, g_wo);
    float* q   = (float*)qv;
    float* k   = (float*)kv;
    float* v   = (float*)vv;
    float* ctx = (float*)cv;
    float* xt  = (float*)xtv;
    float* wq  = (float*)wqv;
    float* wk  = (float*)wkv;
    float* wv  = (float*)wvv;
    float* wo  = (float*)wov;

    // Pre-round inputs to tf32 bits (bit-identical to converting at stage time)
    const int nx4 = Mtot * Dc / 4;     // 1,048,576
    const int nw4 = Dc * Dc / 4;       // 262,144
    tf32_convert<<<nx4 / 256, 256>>>(x,  xt, nx4);
    tf32_convert<<<nw4 / 256, 256>>>(Wq, wq, nw4);
    tf32_convert<<<nw4 / 256, 256>>>(Wk, wk, nw4);
    tf32_convert<<<nw4 / 256, 256>>>(Wv, wv, nw4);
    tf32_convert<<<nw4 / 256, 256>>>(Wo, wo, nw4);

    dim3 g1(Dc / 128, Mtot / 128);   // (8, 32)
    mma_gemm<1><<<g1, 256>>>(xt, wq, bq, q, 0.125f);   // 1/sqrt(64)
    mma_gemm<1><<<g1, 256>>>(xt, wk, bk, k, 1.0f);
    mma_gemm<1><<<g1, 256>>>(xt, wv, bv, v, 1.0f);

    fattn<<<dim3(Sc / 128, Bc * Hc), 256>>>(q, k, v, mask, ctx);

    mma_gemm<0><<<g1, 256>>>(ctx, wo, bo, out, 1.0f);
}